// round 1
// baseline (speedup 1.0000x reference)
#include <cuda_runtime.h>
#include <cuda_bf16.h>
#include <cstdint>

// ---------------------------------------------------------------------------
// GraphSAGE, 3 layers, mean aggregation.
//   deg[d]   = #in-edges of d ; inv_deg = 1/max(deg,1)
//   layer l: y = h @ Wneigh_l            (transform FIRST, then aggregate:
//            agg[d] = sum_{e: dst=d} y[src_e]       linear ops commute)
//            h' = act(h @ Wself_l + agg * inv_deg + b_l)
// ---------------------------------------------------------------------------

#define MAXN 100000
#define MAXE 1600000

__device__ float g_h1[(size_t)MAXN * 128];
__device__ float g_h2[(size_t)MAXN * 128];
__device__ float g_y [(size_t)MAXN * 128];
__device__ float g_agg[(size_t)MAXN * 128];
__device__ float g_deg[MAXN];

// ---------------------------------------------------------------------------
// degree kernels
// ---------------------------------------------------------------------------
__global__ void count_deg_kernel(const int* __restrict__ dst, float* __restrict__ deg, int E) {
    int i = blockIdx.x * blockDim.x + threadIdx.x;
    if (i < E) atomicAdd(&deg[dst[i]], 1.0f);
}

__global__ void make_inv_deg_kernel(float* __restrict__ deg, int N) {
    int i = blockIdx.x * blockDim.x + threadIdx.x;
    if (i < N) deg[i] = 1.0f / fmaxf(deg[i], 1.0f);
}

// ---------------------------------------------------------------------------
// scatter: agg[dst] += y[src]   (one warp per edge, vectorized row copy)
// ---------------------------------------------------------------------------
template <int FO>
__global__ void scatter_kernel(const float* __restrict__ y,
                               const int* __restrict__ src,
                               const int* __restrict__ dst,
                               float* __restrict__ agg, int E) {
    int warp = (blockIdx.x * blockDim.x + threadIdx.x) >> 5;
    int lane = threadIdx.x & 31;
    if (warp >= E) return;
    int s = src[warp];
    int d = dst[warp];
    if (FO == 128) {
        float4 v = *(const float4*)(y + (size_t)s * 128 + lane * 4);
        float*  a = agg + (size_t)d * 128 + lane * 4;
        atomicAdd(a + 0, v.x);
        atomicAdd(a + 1, v.y);
        atomicAdd(a + 2, v.z);
        atomicAdd(a + 3, v.w);
    } else {  // FO == 64
        float2 v = *(const float2*)(y + (size_t)s * 64 + lane * 2);
        float*  a = agg + (size_t)d * 64 + lane * 2;
        atomicAdd(a + 0, v.x);
        atomicAdd(a + 1, v.y);
    }
}

// ---------------------------------------------------------------------------
// GEMM:  out[M,BN] = A[M,128] @ W[128,BN]   (+ agg*inv_deg + bias, relu)
// Block: 256 threads, computes 128 rows x BN cols. K=128 fits in one tile.
// Thread tile: 8 rows x TN cols (TN = BN/16).
// ---------------------------------------------------------------------------
template <int BN, int TN, bool COMBINE, bool RELU>
__global__ void gemm_kernel(const float* __restrict__ A,
                            const float* __restrict__ W,
                            const float* __restrict__ bias,
                            const float* __restrict__ agg,
                            const float* __restrict__ inv_deg,
                            float* __restrict__ out, int M) {
    constexpr int K = 128;
    extern __shared__ float smem[];
    float* As = smem;                 // [128][128]
    float* Ws = smem + 128 * K;       // [128][BN]

    const int rowBase = blockIdx.x * 128;

    // load A tile (rows >= M -> zeros)
    const float4* A4 = (const float4*)A;
    for (int idx = threadIdx.x; idx < 128 * 32; idx += 256) {
        int r = idx >> 5, kv = idx & 31;
        float4 v = make_float4(0.f, 0.f, 0.f, 0.f);
        int row = rowBase + r;
        if (row < M) v = A4[(size_t)row * 32 + kv];
        *(float4*)(As + r * K + kv * 4) = v;
    }
    // load W (contiguous copy)
    for (int idx = threadIdx.x; idx < K * BN / 4; idx += 256) {
        ((float4*)Ws)[idx] = ((const float4*)W)[idx];
    }
    __syncthreads();

    const int ty = threadIdx.x >> 4;   // 0..15  (row group)
    const int tx = threadIdx.x & 15;   // 0..15  (col group)

    float acc[8 * TN];
#pragma unroll
    for (int i = 0; i < 8 * TN; i++) acc[i] = 0.f;

    const float* Asp = As + (ty * 8) * K;
    const float* Wsp = Ws + tx * TN;

#pragma unroll 4
    for (int k = 0; k < K; k++) {
        float a[8];
#pragma unroll
        for (int i = 0; i < 8; i++) a[i] = Asp[i * K + k];
        float b[TN];
#pragma unroll
        for (int j = 0; j < TN; j += 4) {
            float4 t = *(const float4*)(Wsp + k * BN + j);
            b[j + 0] = t.x; b[j + 1] = t.y; b[j + 2] = t.z; b[j + 3] = t.w;
        }
#pragma unroll
        for (int i = 0; i < 8; i++)
#pragma unroll
            for (int j = 0; j < TN; j++)
                acc[i * TN + j] = fmaf(a[i], b[j], acc[i * TN + j]);
    }

    // epilogue
    float bvals[TN];
    if (COMBINE) {
#pragma unroll
        for (int j = 0; j < TN; j++) bvals[j] = bias[tx * TN + j];
    }

#pragma unroll
    for (int i = 0; i < 8; i++) {
        int row = rowBase + ty * 8 + i;
        if (row >= M) continue;
        float id = COMBINE ? inv_deg[row] : 0.f;
        size_t base = (size_t)row * BN + tx * TN;
#pragma unroll
        for (int j = 0; j < TN; j += 4) {
            float4 v;
            v.x = acc[i * TN + j + 0];
            v.y = acc[i * TN + j + 1];
            v.z = acc[i * TN + j + 2];
            v.w = acc[i * TN + j + 3];
            if (COMBINE) {
                float4 ag = *(const float4*)(agg + base + j);
                v.x += ag.x * id + bvals[j + 0];
                v.y += ag.y * id + bvals[j + 1];
                v.z += ag.z * id + bvals[j + 2];
                v.w += ag.w * id + bvals[j + 3];
                if (RELU) {
                    v.x = fmaxf(v.x, 0.f); v.y = fmaxf(v.y, 0.f);
                    v.z = fmaxf(v.z, 0.f); v.w = fmaxf(v.w, 0.f);
                }
            }
            *(float4*)(out + base + j) = v;
        }
    }
}

// ---------------------------------------------------------------------------
// launch
// ---------------------------------------------------------------------------
extern "C" void kernel_launch(void* const* d_in, const int* in_sizes, int n_in,
                              void* d_out, int out_size) {
    const float* x   = (const float*)d_in[0];
    const int*   src = (const int*)d_in[1];
    const int*   dst = (const int*)d_in[2];
    const float* Ws0 = (const float*)d_in[3];
    const float* Wn0 = (const float*)d_in[4];
    const float* b0  = (const float*)d_in[5];
    const float* Ws1 = (const float*)d_in[6];
    const float* Wn1 = (const float*)d_in[7];
    const float* b1  = (const float*)d_in[8];
    const float* Ws2 = (const float*)d_in[9];
    const float* Wn2 = (const float*)d_in[10];
    const float* b2  = (const float*)d_in[11];
    float* out = (float*)d_out;

    const int M = in_sizes[0] / 128;   // 100000
    const int E = in_sizes[1];         // 1600000

    float *h1, *h2, *y, *agg, *deg;
    cudaGetSymbolAddress((void**)&h1,  g_h1);
    cudaGetSymbolAddress((void**)&h2,  g_h2);
    cudaGetSymbolAddress((void**)&y,   g_y);
    cudaGetSymbolAddress((void**)&agg, g_agg);
    cudaGetSymbolAddress((void**)&deg, g_deg);

    const int SMEM128 = (128 * 128 + 128 * 128) * 4;  // 128 KB
    const int SMEM64  = (128 * 128 + 128 * 64) * 4;   // 96 KB
    cudaFuncSetAttribute(gemm_kernel<128, 8, false, false>,
                         cudaFuncAttributeMaxDynamicSharedMemorySize, SMEM128);
    cudaFuncSetAttribute(gemm_kernel<128, 8, true, true>,
                         cudaFuncAttributeMaxDynamicSharedMemorySize, SMEM128);
    cudaFuncSetAttribute(gemm_kernel<64, 4, false, false>,
                         cudaFuncAttributeMaxDynamicSharedMemorySize, SMEM64);
    cudaFuncSetAttribute(gemm_kernel<64, 4, true, false>,
                         cudaFuncAttributeMaxDynamicSharedMemorySize, SMEM64);

    const int gemmBlocks = (M + 127) / 128;
    const int edgeBlocks = (E + 255) / 256;          // 1 thread / edge
    const int scatBlocks = (E * 32 + 255) / 256;     // 1 warp / edge
    const int nodeBlocks = (M + 255) / 256;

    // degrees
    cudaMemsetAsync(deg, 0, (size_t)M * sizeof(float));
    count_deg_kernel<<<edgeBlocks, 256>>>(dst, deg, E);
    make_inv_deg_kernel<<<nodeBlocks, 256>>>(deg, M);

    // ---- layer 0: x -> h1 (relu) ----
    gemm_kernel<128, 8, false, false><<<gemmBlocks, 256, SMEM128>>>(
        x, Wn0, nullptr, nullptr, nullptr, y, M);
    cudaMemsetAsync(agg, 0, (size_t)M * 128 * sizeof(float));
    scatter_kernel<128><<<scatBlocks, 256>>>(y, src, dst, agg, E);
    gemm_kernel<128, 8, true, true><<<gemmBlocks, 256, SMEM128>>>(
        x, Ws0, b0, agg, deg, h1, M);

    // ---- layer 1: h1 -> h2 (relu) ----
    gemm_kernel<128, 8, false, false><<<gemmBlocks, 256, SMEM128>>>(
        h1, Wn1, nullptr, nullptr, nullptr, y, M);
    cudaMemsetAsync(agg, 0, (size_t)M * 128 * sizeof(float));
    scatter_kernel<128><<<scatBlocks, 256>>>(y, src, dst, agg, E);
    gemm_kernel<128, 8, true, true><<<gemmBlocks, 256, SMEM128>>>(
        h1, Ws1, b1, agg, deg, h2, M);

    // ---- layer 2: h2 -> out (no relu, FO=64) ----
    gemm_kernel<64, 4, false, false><<<gemmBlocks, 256, SMEM64>>>(
        h2, Wn2, nullptr, nullptr, nullptr, y, M);
    cudaMemsetAsync(agg, 0, (size_t)M * 64 * sizeof(float));
    scatter_kernel<64><<<scatBlocks, 256>>>(y, src, dst, agg, E);
    gemm_kernel<64, 4, true, false><<<gemmBlocks, 256, SMEM64>>>(
        h2, Ws2, b2, agg, deg, out, M);
}

// round 2
// speedup vs baseline: 1.6292x; 1.6292x over previous
#include <cuda_runtime.h>
#include <cuda_bf16.h>
#include <cstdint>

// ---------------------------------------------------------------------------
// GraphSAGE, 3 layers, mean aggregation.
// agg computed by transform-then-aggregate (linearity):
//   y = h @ Wneigh ;  agg[d] = mean_{e: dst=d} y[src_e]
//   h' = act(h @ Wself + agg + b)
// Aggregation is atomic-free: dst-sorted CSR built per launch, warp-per-node
// gather sums y rows in registers and writes once (scaled by inv_deg).
// ---------------------------------------------------------------------------

#define MAXN 100000
#define MAXE 1600000
#define SCAN_THREADS 1024

__device__ float g_h1[(size_t)MAXN * 128];
__device__ float g_h2[(size_t)MAXN * 128];
__device__ float g_y [(size_t)MAXN * 128];
__device__ float g_agg[(size_t)MAXN * 128];
__device__ float g_invdeg[MAXN];
__device__ int   g_degi[MAXN];
__device__ int   g_rowstart[MAXN + 1];
__device__ int   g_cursor[MAXN];
__device__ int   g_colsrc[MAXE];

// ---------------------------------------------------------------------------
// CSR build
// ---------------------------------------------------------------------------
__global__ void count_deg_kernel(const int* __restrict__ dst, int* __restrict__ degi, int E) {
    int i = blockIdx.x * blockDim.x + threadIdx.x;
    if (i < E) atomicAdd(&degi[dst[i]], 1);
}

// single-block scan: exclusive prefix over degi -> rowstart, plus inv_deg
__global__ void scan_kernel(const int* __restrict__ degi,
                            int* __restrict__ rowstart,
                            float* __restrict__ invdeg, int N) {
    __shared__ int ssum[SCAN_THREADS];
    int t = threadIdx.x;
    int chunk = (N + SCAN_THREADS - 1) / SCAN_THREADS;
    int beg = t * chunk, end = min(N, beg + chunk);

    int s = 0;
    for (int i = beg; i < end; i++) s += degi[i];
    ssum[t] = s;
    __syncthreads();

    // Hillis-Steele inclusive scan
    for (int off = 1; off < SCAN_THREADS; off <<= 1) {
        int v = (t >= off) ? ssum[t - off] : 0;
        __syncthreads();
        ssum[t] += v;
        __syncthreads();
    }
    int run = ssum[t] - s;  // exclusive prefix for this thread's chunk
    for (int i = beg; i < end; i++) {
        int d = degi[i];
        rowstart[i] = run;
        invdeg[i] = 1.0f / fmaxf((float)d, 1.0f);
        run += d;
    }
    if (t == SCAN_THREADS - 1) rowstart[N] = run;
}

__global__ void fill_kernel(const int* __restrict__ src,
                            const int* __restrict__ dst,
                            const int* __restrict__ rowstart,
                            int* __restrict__ cursor,
                            int* __restrict__ colsrc, int E) {
    int i = blockIdx.x * blockDim.x + threadIdx.x;
    if (i >= E) return;
    int d = dst[i];
    int pos = rowstart[d] + atomicAdd(&cursor[d], 1);
    colsrc[pos] = src[i];
}

// ---------------------------------------------------------------------------
// gather: agg[n] = inv_deg[n] * sum_{j in row(n)} y[colsrc[j]]   (warp/node)
// ---------------------------------------------------------------------------
template <int FO>
__global__ void gather_kernel(const float* __restrict__ y,
                              const int* __restrict__ rowstart,
                              const int* __restrict__ colsrc,
                              const float* __restrict__ invdeg,
                              float* __restrict__ agg, int N) {
    int warp = (blockIdx.x * blockDim.x + threadIdx.x) >> 5;
    int lane = threadIdx.x & 31;
    if (warp >= N) return;
    int beg = rowstart[warp];
    int end = rowstart[warp + 1];

    if (FO == 128) {
        const float* yb = y + lane * 4;
        float4 acc = make_float4(0.f, 0.f, 0.f, 0.f);
        int j = beg;
        for (; j + 4 <= end; j += 4) {
            int s0 = __ldg(colsrc + j + 0);
            int s1 = __ldg(colsrc + j + 1);
            int s2 = __ldg(colsrc + j + 2);
            int s3 = __ldg(colsrc + j + 3);
            float4 v0 = *(const float4*)(yb + (size_t)s0 * 128);
            float4 v1 = *(const float4*)(yb + (size_t)s1 * 128);
            float4 v2 = *(const float4*)(yb + (size_t)s2 * 128);
            float4 v3 = *(const float4*)(yb + (size_t)s3 * 128);
            acc.x += v0.x + v1.x + v2.x + v3.x;
            acc.y += v0.y + v1.y + v2.y + v3.y;
            acc.z += v0.z + v1.z + v2.z + v3.z;
            acc.w += v0.w + v1.w + v2.w + v3.w;
        }
        for (; j < end; j++) {
            int s = __ldg(colsrc + j);
            float4 v = *(const float4*)(yb + (size_t)s * 128);
            acc.x += v.x; acc.y += v.y; acc.z += v.z; acc.w += v.w;
        }
        float id = invdeg[warp];
        acc.x *= id; acc.y *= id; acc.z *= id; acc.w *= id;
        *(float4*)(agg + (size_t)warp * 128 + lane * 4) = acc;
    } else {  // FO == 64
        const float* yb = y + lane * 2;
        float2 acc = make_float2(0.f, 0.f);
        int j = beg;
        for (; j + 4 <= end; j += 4) {
            int s0 = __ldg(colsrc + j + 0);
            int s1 = __ldg(colsrc + j + 1);
            int s2 = __ldg(colsrc + j + 2);
            int s3 = __ldg(colsrc + j + 3);
            float2 v0 = *(const float2*)(yb + (size_t)s0 * 64);
            float2 v1 = *(const float2*)(yb + (size_t)s1 * 64);
            float2 v2 = *(const float2*)(yb + (size_t)s2 * 64);
            float2 v3 = *(const float2*)(yb + (size_t)s3 * 64);
            acc.x += v0.x + v1.x + v2.x + v3.x;
            acc.y += v0.y + v1.y + v2.y + v3.y;
        }
        for (; j < end; j++) {
            int s = __ldg(colsrc + j);
            float2 v = *(const float2*)(yb + (size_t)s * 64);
            acc.x += v.x; acc.y += v.y;
        }
        float id = invdeg[warp];
        acc.x *= id; acc.y *= id;
        *(float2*)(agg + (size_t)warp * 64 + lane * 2) = acc;
    }
}

// ---------------------------------------------------------------------------
// GEMM:  out[M,BN] = A[M,128] @ W[128,BN]   (+ agg + bias, relu)
// Block: 256 threads, 128 rows x BN cols, K=128 in one smem tile.
// ---------------------------------------------------------------------------
template <int BN, int TN, bool COMBINE, bool RELU>
__global__ void gemm_kernel(const float* __restrict__ A,
                            const float* __restrict__ W,
                            const float* __restrict__ bias,
                            const float* __restrict__ agg,
                            float* __restrict__ out, int M) {
    constexpr int K = 128;
    extern __shared__ float smem[];
    float* As = smem;                 // [128][128]
    float* Ws = smem + 128 * K;       // [128][BN]

    const int rowBase = blockIdx.x * 128;

    const float4* A4 = (const float4*)A;
    for (int idx = threadIdx.x; idx < 128 * 32; idx += 256) {
        int r = idx >> 5, kv = idx & 31;
        float4 v = make_float4(0.f, 0.f, 0.f, 0.f);
        int row = rowBase + r;
        if (row < M) v = A4[(size_t)row * 32 + kv];
        *(float4*)(As + r * K + kv * 4) = v;
    }
    for (int idx = threadIdx.x; idx < K * BN / 4; idx += 256) {
        ((float4*)Ws)[idx] = ((const float4*)W)[idx];
    }
    __syncthreads();

    const int ty = threadIdx.x >> 4;
    const int tx = threadIdx.x & 15;

    float acc[8 * TN];
#pragma unroll
    for (int i = 0; i < 8 * TN; i++) acc[i] = 0.f;

    const float* Asp = As + (ty * 8) * K;
    const float* Wsp = Ws + tx * TN;

#pragma unroll 4
    for (int k = 0; k < K; k++) {
        float a[8];
#pragma unroll
        for (int i = 0; i < 8; i++) a[i] = Asp[i * K + k];
        float b[TN];
#pragma unroll
        for (int j = 0; j < TN; j += 4) {
            float4 t = *(const float4*)(Wsp + k * BN + j);
            b[j + 0] = t.x; b[j + 1] = t.y; b[j + 2] = t.z; b[j + 3] = t.w;
        }
#pragma unroll
        for (int i = 0; i < 8; i++)
#pragma unroll
            for (int j = 0; j < TN; j++)
                acc[i * TN + j] = fmaf(a[i], b[j], acc[i * TN + j]);
    }

    float bvals[TN];
    if (COMBINE) {
#pragma unroll
        for (int j = 0; j < TN; j++) bvals[j] = bias[tx * TN + j];
    }

#pragma unroll
    for (int i = 0; i < 8; i++) {
        int row = rowBase + ty * 8 + i;
        if (row >= M) continue;
        size_t base = (size_t)row * BN + tx * TN;
#pragma unroll
        for (int j = 0; j < TN; j += 4) {
            float4 v;
            v.x = acc[i * TN + j + 0];
            v.y = acc[i * TN + j + 1];
            v.z = acc[i * TN + j + 2];
            v.w = acc[i * TN + j + 3];
            if (COMBINE) {
                float4 ag = *(const float4*)(agg + base + j);
                v.x += ag.x + bvals[j + 0];
                v.y += ag.y + bvals[j + 1];
                v.z += ag.z + bvals[j + 2];
                v.w += ag.w + bvals[j + 3];
                if (RELU) {
                    v.x = fmaxf(v.x, 0.f); v.y = fmaxf(v.y, 0.f);
                    v.z = fmaxf(v.z, 0.f); v.w = fmaxf(v.w, 0.f);
                }
            }
            *(float4*)(out + base + j) = v;
        }
    }
}

// ---------------------------------------------------------------------------
// launch
// ---------------------------------------------------------------------------
extern "C" void kernel_launch(void* const* d_in, const int* in_sizes, int n_in,
                              void* d_out, int out_size) {
    const float* x   = (const float*)d_in[0];
    const int*   src = (const int*)d_in[1];
    const int*   dst = (const int*)d_in[2];
    const float* Ws0 = (const float*)d_in[3];
    const float* Wn0 = (const float*)d_in[4];
    const float* b0  = (const float*)d_in[5];
    const float* Ws1 = (const float*)d_in[6];
    const float* Wn1 = (const float*)d_in[7];
    const float* b1  = (const float*)d_in[8];
    const float* Ws2 = (const float*)d_in[9];
    const float* Wn2 = (const float*)d_in[10];
    const float* b2  = (const float*)d_in[11];
    float* out = (float*)d_out;

    const int M = in_sizes[0] / 128;   // 100000
    const int E = in_sizes[1];         // 1600000

    float *h1, *h2, *y, *agg, *invdeg;
    int *degi, *rowstart, *cursor, *colsrc;
    cudaGetSymbolAddress((void**)&h1,  g_h1);
    cudaGetSymbolAddress((void**)&h2,  g_h2);
    cudaGetSymbolAddress((void**)&y,   g_y);
    cudaGetSymbolAddress((void**)&agg, g_agg);
    cudaGetSymbolAddress((void**)&invdeg, g_invdeg);
    cudaGetSymbolAddress((void**)&degi, g_degi);
    cudaGetSymbolAddress((void**)&rowstart, g_rowstart);
    cudaGetSymbolAddress((void**)&cursor, g_cursor);
    cudaGetSymbolAddress((void**)&colsrc, g_colsrc);

    const int SMEM128 = (128 * 128 + 128 * 128) * 4;
    const int SMEM64  = (128 * 128 + 128 * 64) * 4;
    cudaFuncSetAttribute(gemm_kernel<128, 8, false, false>,
                         cudaFuncAttributeMaxDynamicSharedMemorySize, SMEM128);
    cudaFuncSetAttribute(gemm_kernel<128, 8, true, true>,
                         cudaFuncAttributeMaxDynamicSharedMemorySize, SMEM128);
    cudaFuncSetAttribute(gemm_kernel<64, 4, false, false>,
                         cudaFuncAttributeMaxDynamicSharedMemorySize, SMEM64);
    cudaFuncSetAttribute(gemm_kernel<64, 4, true, false>,
                         cudaFuncAttributeMaxDynamicSharedMemorySize, SMEM64);

    const int gemmBlocks  = (M + 127) / 128;
    const int edgeBlocks  = (E + 255) / 256;
    const int gatherBlocks = (M * 32 + 255) / 256;   // warp per node

    // ---- CSR build (dst-sorted) ----
    cudaMemsetAsync(degi, 0, (size_t)M * sizeof(int));
    cudaMemsetAsync(cursor, 0, (size_t)M * sizeof(int));
    count_deg_kernel<<<edgeBlocks, 256>>>(dst, degi, E);
    scan_kernel<<<1, SCAN_THREADS>>>(degi, rowstart, invdeg, M);
    fill_kernel<<<edgeBlocks, 256>>>(src, dst, rowstart, cursor, colsrc, E);

    // ---- layer 0: x -> h1 (relu) ----
    gemm_kernel<128, 8, false, false><<<gemmBlocks, 256, SMEM128>>>(
        x, Wn0, nullptr, nullptr, y, M);
    gather_kernel<128><<<gatherBlocks, 256>>>(y, rowstart, colsrc, invdeg, agg, M);
    gemm_kernel<128, 8, true, true><<<gemmBlocks, 256, SMEM128>>>(
        x, Ws0, b0, agg, h1, M);

    // ---- layer 1: h1 -> h2 (relu) ----
    gemm_kernel<128, 8, false, false><<<gemmBlocks, 256, SMEM128>>>(
        h1, Wn1, nullptr, nullptr, y, M);
    gather_kernel<128><<<gatherBlocks, 256>>>(y, rowstart, colsrc, invdeg, agg, M);
    gemm_kernel<128, 8, true, true><<<gemmBlocks, 256, SMEM128>>>(
        h1, Ws1, b1, agg, h2, M);

    // ---- layer 2: h2 -> out (no relu, FO=64) ----
    gemm_kernel<64, 4, false, false><<<gemmBlocks, 256, SMEM64>>>(
        h2, Wn2, nullptr, nullptr, y, M);
    gather_kernel<64><<<gatherBlocks, 256>>>(y, rowstart, colsrc, invdeg, agg, M);
    gemm_kernel<64, 4, true, false><<<gemmBlocks, 256, SMEM64>>>(
        h2, Ws2, b2, agg, out, M);
}

// round 3
// speedup vs baseline: 2.2114x; 1.3574x over previous
#include <cuda_runtime.h>
#include <cuda_bf16.h>
#include <cstdint>

// ---------------------------------------------------------------------------
// GraphSAGE, 3 layers, mean aggregation. Aggregate-then-transform:
//   agg = mean_{e: dst=d} h[src_e]          (CSR gather, atomic-free)
//   h'  = act([h | agg] @ [Wself; Wneigh] + b)   (dual-A GEMM, K=256)
// ---------------------------------------------------------------------------

#define MAXN 100000
#define MAXE 1600000
#define SCAN_THREADS 1024

__device__ float g_h1[(size_t)MAXN * 128];
__device__ float g_h2[(size_t)MAXN * 128];
__device__ float g_agg[(size_t)MAXN * 128];
__device__ float g_invdeg[MAXN];
__device__ int   g_degi[MAXN];
__device__ int   g_rowstart[MAXN + 1];
__device__ int   g_cursor[MAXN];
__device__ int   g_colsrc[MAXE];

// ---------------------------------------------------------------------------
// CSR build
// ---------------------------------------------------------------------------
__global__ void count_deg_kernel(const int* __restrict__ dst, int* __restrict__ degi, int E) {
    int i = blockIdx.x * blockDim.x + threadIdx.x;
    if (i < E) atomicAdd(&degi[dst[i]], 1);
}

__global__ void scan_kernel(const int* __restrict__ degi,
                            int* __restrict__ rowstart,
                            float* __restrict__ invdeg, int N) {
    __shared__ int ssum[SCAN_THREADS];
    int t = threadIdx.x;
    int chunk = (N + SCAN_THREADS - 1) / SCAN_THREADS;
    int beg = t * chunk, end = min(N, beg + chunk);

    int s = 0;
    for (int i = beg; i < end; i++) s += degi[i];
    ssum[t] = s;
    __syncthreads();

    for (int off = 1; off < SCAN_THREADS; off <<= 1) {
        int v = (t >= off) ? ssum[t - off] : 0;
        __syncthreads();
        ssum[t] += v;
        __syncthreads();
    }
    int run = ssum[t] - s;
    for (int i = beg; i < end; i++) {
        int d = degi[i];
        rowstart[i] = run;
        invdeg[i] = 1.0f / fmaxf((float)d, 1.0f);
        run += d;
    }
    if (t == SCAN_THREADS - 1) rowstart[N] = run;
}

__global__ void fill_kernel(const int* __restrict__ src,
                            const int* __restrict__ dst,
                            const int* __restrict__ rowstart,
                            int* __restrict__ cursor,
                            int* __restrict__ colsrc, int E) {
    int i = blockIdx.x * blockDim.x + threadIdx.x;
    if (i >= E) return;
    int d = dst[i];
    int pos = rowstart[d] + atomicAdd(&cursor[d], 1);
    colsrc[pos] = src[i];
}

// ---------------------------------------------------------------------------
// gather: agg[n] = inv_deg[n] * sum_{j in row(n)} h[colsrc[j]]   (warp/node)
// ---------------------------------------------------------------------------
__global__ void gather_kernel(const float* __restrict__ h,
                              const int* __restrict__ rowstart,
                              const int* __restrict__ colsrc,
                              const float* __restrict__ invdeg,
                              float* __restrict__ agg, int N) {
    int warp = (blockIdx.x * blockDim.x + threadIdx.x) >> 5;
    int lane = threadIdx.x & 31;
    if (warp >= N) return;
    int beg = rowstart[warp];
    int end = rowstart[warp + 1];

    const float* hb = h + lane * 4;
    float4 acc = make_float4(0.f, 0.f, 0.f, 0.f);
    int j = beg;
    for (; j + 4 <= end; j += 4) {
        int s0 = __ldg(colsrc + j + 0);
        int s1 = __ldg(colsrc + j + 1);
        int s2 = __ldg(colsrc + j + 2);
        int s3 = __ldg(colsrc + j + 3);
        float4 v0 = *(const float4*)(hb + (size_t)s0 * 128);
        float4 v1 = *(const float4*)(hb + (size_t)s1 * 128);
        float4 v2 = *(const float4*)(hb + (size_t)s2 * 128);
        float4 v3 = *(const float4*)(hb + (size_t)s3 * 128);
        acc.x += v0.x + v1.x + v2.x + v3.x;
        acc.y += v0.y + v1.y + v2.y + v3.y;
        acc.z += v0.z + v1.z + v2.z + v3.z;
        acc.w += v0.w + v1.w + v2.w + v3.w;
    }
    for (; j < end; j++) {
        int s = __ldg(colsrc + j);
        float4 v = *(const float4*)(hb + (size_t)s * 128);
        acc.x += v.x; acc.y += v.y; acc.z += v.z; acc.w += v.w;
    }
    float id = invdeg[warp];
    acc.x *= id; acc.y *= id; acc.z *= id; acc.w *= id;
    *(float4*)(agg + (size_t)warp * 128 + lane * 4) = acc;
}

// ---------------------------------------------------------------------------
// dual-A GEMM:  out[M,BN] = A1[M,128]@W1[128,BN] + A2[M,128]@W2[128,BN] + b
// Block: 256 threads, 128 rows x BN cols. K-tiled (KT=16), double-buffered.
// Thread tile 8 x TN (TN = BN/16).
// ---------------------------------------------------------------------------
template <int BN, bool RELU>
__launch_bounds__(256, 2)
__global__ void gemm2_kernel(const float* __restrict__ A1,
                             const float* __restrict__ A2,
                             const float* __restrict__ W1,
                             const float* __restrict__ W2,
                             const float* __restrict__ bias,
                             float* __restrict__ out, int M) {
    constexpr int KT = 16;
    constexpr int NS = 16;           // 256 / KT total k-steps (8 per A)
    constexpr int PAD = 4;
    constexpr int TN = BN / 16;
    constexpr int NB4 = (KT * BN / 4) / 256;   // float4 B loads per thread

    __shared__ float As[2][KT][128 + PAD];
    __shared__ float Bs[2][KT][BN];

    const int tid = threadIdx.x;
    const int rowBase = blockIdx.x * 128;
    const int ty = tid >> 4;
    const int tx = tid & 15;

    float acc[8 * TN];
#pragma unroll
    for (int i = 0; i < 8 * TN; i++) acc[i] = 0.f;

    float4 ra[2];
    float4 rb[NB4 > 0 ? NB4 : 1];

    // ---- prologue: fill buffer 0 ----
    {
        const float* A = A1;
        const float* W = W1;
#pragma unroll
        for (int i = 0; i < 2; i++) {
            int idx = tid + i * 256;
            int r = idx >> 2, kq = idx & 3;
            int row = rowBase + r;
            float4 v = make_float4(0.f, 0.f, 0.f, 0.f);
            if (row < M) v = *(const float4*)(A + (size_t)row * 128 + kq * 4);
            As[0][kq * 4 + 0][r] = v.x;
            As[0][kq * 4 + 1][r] = v.y;
            As[0][kq * 4 + 2][r] = v.z;
            As[0][kq * 4 + 3][r] = v.w;
        }
#pragma unroll
        for (int i = 0; i < NB4; i++) {
            int idx = tid + i * 256;
            int kk = idx / (BN / 4), cc = idx % (BN / 4);
            *(float4*)&Bs[0][kk][cc * 4] = *(const float4*)(W + (size_t)kk * BN + cc * 4);
        }
    }
    __syncthreads();

    // ---- main loop ----
#pragma unroll 1
    for (int s = 0; s < NS; s++) {
        const int buf = s & 1;

        // prefetch step s+1 into registers
        if (s + 1 < NS) {
            const float* A = (s + 1 < 8) ? A1 : A2;
            const float* W = (s + 1 < 8) ? W1 : W2;
            const int k0 = ((s + 1) & 7) * KT;
#pragma unroll
            for (int i = 0; i < 2; i++) {
                int idx = tid + i * 256;
                int r = idx >> 2, kq = idx & 3;
                int row = rowBase + r;
                ra[i] = make_float4(0.f, 0.f, 0.f, 0.f);
                if (row < M) ra[i] = *(const float4*)(A + (size_t)row * 128 + k0 + kq * 4);
            }
#pragma unroll
            for (int i = 0; i < NB4; i++) {
                int idx = tid + i * 256;
                int kk = idx / (BN / 4), cc = idx % (BN / 4);
                rb[i] = *(const float4*)(W + (size_t)(k0 + kk) * BN + cc * 4);
            }
        }

        // compute on buf
#pragma unroll
        for (int k = 0; k < KT; k++) {
            float a[8];
            *(float4*)&a[0] = *(const float4*)&As[buf][k][ty * 8];
            *(float4*)&a[4] = *(const float4*)&As[buf][k][ty * 8 + 4];
            float b[TN];
#pragma unroll
            for (int j = 0; j < TN; j += 4)
                *(float4*)&b[j] = *(const float4*)&Bs[buf][k][tx * TN + j];
#pragma unroll
            for (int i = 0; i < 8; i++)
#pragma unroll
                for (int j = 0; j < TN; j++)
                    acc[i * TN + j] = fmaf(a[i], b[j], acc[i * TN + j]);
        }

        // store prefetched regs into other buffer
        if (s + 1 < NS) {
            const int nbuf = buf ^ 1;
#pragma unroll
            for (int i = 0; i < 2; i++) {
                int idx = tid + i * 256;
                int r = idx >> 2, kq = idx & 3;
                As[nbuf][kq * 4 + 0][r] = ra[i].x;
                As[nbuf][kq * 4 + 1][r] = ra[i].y;
                As[nbuf][kq * 4 + 2][r] = ra[i].z;
                As[nbuf][kq * 4 + 3][r] = ra[i].w;
            }
#pragma unroll
            for (int i = 0; i < NB4; i++) {
                int idx = tid + i * 256;
                int kk = idx / (BN / 4), cc = idx % (BN / 4);
                *(float4*)&Bs[nbuf][kk][cc * 4] = rb[i];
            }
            __syncthreads();
        }
    }

    // ---- epilogue ----
    float bvals[TN];
#pragma unroll
    for (int j = 0; j < TN; j++) bvals[j] = bias[tx * TN + j];

#pragma unroll
    for (int i = 0; i < 8; i++) {
        int row = rowBase + ty * 8 + i;
        if (row >= M) continue;
        size_t base = (size_t)row * BN + tx * TN;
#pragma unroll
        for (int j = 0; j < TN; j += 4) {
            float4 v;
            v.x = acc[i * TN + j + 0] + bvals[j + 0];
            v.y = acc[i * TN + j + 1] + bvals[j + 1];
            v.z = acc[i * TN + j + 2] + bvals[j + 2];
            v.w = acc[i * TN + j + 3] + bvals[j + 3];
            if (RELU) {
                v.x = fmaxf(v.x, 0.f); v.y = fmaxf(v.y, 0.f);
                v.z = fmaxf(v.z, 0.f); v.w = fmaxf(v.w, 0.f);
            }
            *(float4*)(out + base + j) = v;
        }
    }
}

// ---------------------------------------------------------------------------
// launch
// ---------------------------------------------------------------------------
extern "C" void kernel_launch(void* const* d_in, const int* in_sizes, int n_in,
                              void* d_out, int out_size) {
    const float* x   = (const float*)d_in[0];
    const int*   src = (const int*)d_in[1];
    const int*   dst = (const int*)d_in[2];
    const float* Ws0 = (const float*)d_in[3];
    const float* Wn0 = (const float*)d_in[4];
    const float* b0  = (const float*)d_in[5];
    const float* Ws1 = (const float*)d_in[6];
    const float* Wn1 = (const float*)d_in[7];
    const float* b1  = (const float*)d_in[8];
    const float* Ws2 = (const float*)d_in[9];
    const float* Wn2 = (const float*)d_in[10];
    const float* b2  = (const float*)d_in[11];
    float* out = (float*)d_out;

    const int M = in_sizes[0] / 128;   // 100000
    const int E = in_sizes[1];         // 1600000

    float *h1, *h2, *agg, *invdeg;
    int *degi, *rowstart, *cursor, *colsrc;
    cudaGetSymbolAddress((void**)&h1,  g_h1);
    cudaGetSymbolAddress((void**)&h2,  g_h2);
    cudaGetSymbolAddress((void**)&agg, g_agg);
    cudaGetSymbolAddress((void**)&invdeg, g_invdeg);
    cudaGetSymbolAddress((void**)&degi, g_degi);
    cudaGetSymbolAddress((void**)&rowstart, g_rowstart);
    cudaGetSymbolAddress((void**)&cursor, g_cursor);
    cudaGetSymbolAddress((void**)&colsrc, g_colsrc);

    const int gemmBlocks   = (M + 127) / 128;
    const int edgeBlocks   = (E + 255) / 256;
    const int gatherBlocks = (M * 32 + 255) / 256;   // warp per node

    // ---- CSR build (dst-sorted) ----
    cudaMemsetAsync(degi, 0, (size_t)M * sizeof(int));
    cudaMemsetAsync(cursor, 0, (size_t)M * sizeof(int));
    count_deg_kernel<<<edgeBlocks, 256>>>(dst, degi, E);
    scan_kernel<<<1, SCAN_THREADS>>>(degi, rowstart, invdeg, M);
    fill_kernel<<<edgeBlocks, 256>>>(src, dst, rowstart, cursor, colsrc, E);

    // ---- layer 0: h1 = relu(x@Ws0 + agg(x)@Wn0 + b0) ----
    gather_kernel<<<gatherBlocks, 256>>>(x, rowstart, colsrc, invdeg, agg, M);
    gemm2_kernel<128, true><<<gemmBlocks, 256>>>(x, agg, Ws0, Wn0, b0, h1, M);

    // ---- layer 1 ----
    gather_kernel<<<gatherBlocks, 256>>>(h1, rowstart, colsrc, invdeg, agg, M);
    gemm2_kernel<128, true><<<gemmBlocks, 256>>>(h1, agg, Ws1, Wn1, b1, h2, M);

    // ---- layer 2 (no relu, BN=64) ----
    gather_kernel<<<gatherBlocks, 256>>>(h2, rowstart, colsrc, invdeg, agg, M);
    gemm2_kernel<64, false><<<gemmBlocks, 256>>>(h2, agg, Ws2, Wn2, b2, out, M);
}

// round 4
// speedup vs baseline: 3.5629x; 1.6111x over previous
#include <cuda_runtime.h>
#include <cuda_bf16.h>
#include <cstdint>

// ---------------------------------------------------------------------------
// GraphSAGE, 3 layers, mean aggregation. Aggregate-then-transform:
//   agg = mean_{e: dst=d} h[src_e]          (CSR gather, atomic-free)
//   h'  = act([h | agg] @ [Wself; Wneigh] + b)   (dual-A tf32 MMA GEMM, K=256)
// ---------------------------------------------------------------------------

#define MAXN 100000
#define MAXE 1600000
#define SCAN_THREADS 1024

__device__ float g_h1[(size_t)MAXN * 128];
__device__ float g_h2[(size_t)MAXN * 128];
__device__ float g_agg[(size_t)MAXN * 128];
__device__ float g_invdeg[MAXN];
__device__ int   g_degi[MAXN];
__device__ int   g_rowstart[MAXN + 1];
__device__ int   g_cursor[MAXN];
__device__ int   g_colsrc[MAXE];

// ---------------------------------------------------------------------------
// CSR build
// ---------------------------------------------------------------------------
__global__ void count_deg_kernel(const int* __restrict__ dst, int* __restrict__ degi, int E) {
    int i = blockIdx.x * blockDim.x + threadIdx.x;
    if (i < E) atomicAdd(&degi[dst[i]], 1);
}

__global__ void scan_kernel(const int* __restrict__ degi,
                            int* __restrict__ rowstart,
                            float* __restrict__ invdeg, int N) {
    __shared__ int ssum[SCAN_THREADS];
    int t = threadIdx.x;
    int chunk = (N + SCAN_THREADS - 1) / SCAN_THREADS;
    int beg = t * chunk, end = min(N, beg + chunk);

    int s = 0;
    for (int i = beg; i < end; i++) s += degi[i];
    ssum[t] = s;
    __syncthreads();

    for (int off = 1; off < SCAN_THREADS; off <<= 1) {
        int v = (t >= off) ? ssum[t - off] : 0;
        __syncthreads();
        ssum[t] += v;
        __syncthreads();
    }
    int run = ssum[t] - s;
    for (int i = beg; i < end; i++) {
        int d = degi[i];
        rowstart[i] = run;
        invdeg[i] = 1.0f / fmaxf((float)d, 1.0f);
        run += d;
    }
    if (t == SCAN_THREADS - 1) rowstart[N] = run;
}

__global__ void fill_kernel(const int* __restrict__ src,
                            const int* __restrict__ dst,
                            const int* __restrict__ rowstart,
                            int* __restrict__ cursor,
                            int* __restrict__ colsrc, int E) {
    int i = blockIdx.x * blockDim.x + threadIdx.x;
    if (i >= E) return;
    int d = dst[i];
    int pos = rowstart[d] + atomicAdd(&cursor[d], 1);
    colsrc[pos] = src[i];
}

// ---------------------------------------------------------------------------
// gather: agg[n] = inv_deg[n] * sum_{j in row(n)} h[colsrc[j]]   (warp/node)
// ---------------------------------------------------------------------------
__global__ void gather_kernel(const float* __restrict__ h,
                              const int* __restrict__ rowstart,
                              const int* __restrict__ colsrc,
                              const float* __restrict__ invdeg,
                              float* __restrict__ agg, int N) {
    int warp = (blockIdx.x * blockDim.x + threadIdx.x) >> 5;
    int lane = threadIdx.x & 31;
    if (warp >= N) return;
    int beg = rowstart[warp];
    int end = rowstart[warp + 1];

    const float* hb = h + lane * 4;
    float4 acc = make_float4(0.f, 0.f, 0.f, 0.f);
    int j = beg;
    for (; j + 4 <= end; j += 4) {
        int s0 = __ldg(colsrc + j + 0);
        int s1 = __ldg(colsrc + j + 1);
        int s2 = __ldg(colsrc + j + 2);
        int s3 = __ldg(colsrc + j + 3);
        float4 v0 = *(const float4*)(hb + (size_t)s0 * 128);
        float4 v1 = *(const float4*)(hb + (size_t)s1 * 128);
        float4 v2 = *(const float4*)(hb + (size_t)s2 * 128);
        float4 v3 = *(const float4*)(hb + (size_t)s3 * 128);
        acc.x += v0.x + v1.x + v2.x + v3.x;
        acc.y += v0.y + v1.y + v2.y + v3.y;
        acc.z += v0.z + v1.z + v2.z + v3.z;
        acc.w += v0.w + v1.w + v2.w + v3.w;
    }
    for (; j < end; j++) {
        int s = __ldg(colsrc + j);
        float4 v = *(const float4*)(hb + (size_t)s * 128);
        acc.x += v.x; acc.y += v.y; acc.z += v.z; acc.w += v.w;
    }
    float id = invdeg[warp];
    acc.x *= id; acc.y *= id; acc.z *= id; acc.w *= id;
    *(float4*)(agg + (size_t)warp * 128 + lane * 4) = acc;
}

// ---------------------------------------------------------------------------
// tf32 helpers
// ---------------------------------------------------------------------------
__device__ __forceinline__ uint32_t f2tf32(float x) {
    uint32_t u;
    asm("cvt.rna.tf32.f32 %0, %1;" : "=r"(u) : "f"(x));
    return u;
}

__device__ __forceinline__ void mma_tf32(float& c0, float& c1, float& c2, float& c3,
                                         uint32_t a0, uint32_t a1, uint32_t a2, uint32_t a3,
                                         uint32_t b0, uint32_t b1) {
    asm volatile(
        "mma.sync.aligned.m16n8k8.row.col.f32.tf32.tf32.f32 "
        "{%0,%1,%2,%3}, {%4,%5,%6,%7}, {%8,%9}, {%0,%1,%2,%3};\n"
        : "+f"(c0), "+f"(c1), "+f"(c2), "+f"(c3)
        : "r"(a0), "r"(a1), "r"(a2), "r"(a3), "r"(b0), "r"(b1));
}

// ---------------------------------------------------------------------------
// dual-A tf32 GEMM:  out[M,BN] = A1[M,128]@W1[128,BN] + A2[M,128]@W2[128,BN]+b
// Block 128 x BN, 256 threads = 8 warps (4m x 2n), warp tile 32 x BN/2.
// mma m16n8k8 tf32, K tiled at KT=16, double-buffered, register prefetch.
// ---------------------------------------------------------------------------
template <int BN, bool RELU>
__launch_bounds__(256, 2)
__global__ void gemm_tc_kernel(const float* __restrict__ A1,
                               const float* __restrict__ A2,
                               const float* __restrict__ W1,
                               const float* __restrict__ W2,
                               const float* __restrict__ bias,
                               float* __restrict__ out, int M) {
    constexpr int KT  = 16;
    constexpr int NS  = 16;            // 256 / KT
    constexpr int APAD = 4;            // A row stride 20 -> conflict-free frags
    constexpr int BPAD = 8;            // B row stride BN+8 (== 8 mod 32)
    constexpr int NF  = BN / 16;       // n-frags per warp (warp n-extent BN/2)
    constexpr int NB4 = (KT * BN / 4) / 256;   // B float4 loads / thread / stage

    __shared__ uint32_t As[2][128][KT + APAD];
    __shared__ uint32_t Bs[2][KT][BN + BPAD];

    const int tid  = threadIdx.x;
    const int wid  = tid >> 5;
    const int lane = tid & 31;
    const int g    = lane >> 2;      // 0..7
    const int t4   = lane & 3;       // 0..3
    const int warpM = wid & 3;       // 0..3  (32-row slice)
    const int warpN = wid >> 2;      // 0..1  (BN/2-col slice)
    const int rowBase = blockIdx.x * 128;

    float acc[2][NF][4];
#pragma unroll
    for (int mf = 0; mf < 2; mf++)
#pragma unroll
        for (int nf = 0; nf < NF; nf++)
#pragma unroll
            for (int r = 0; r < 4; r++) acc[mf][nf][r] = 0.f;

    float4 ra[2];
    float4 rb[NB4];

    // ---- prologue: stage 0 (A1 / W1, k0 = 0) ----
    {
#pragma unroll
        for (int i = 0; i < 2; i++) {
            int f = tid + i * 256;               // 0..511
            int r = f >> 2, kq = f & 3;
            int row = rowBase + r;
            float4 v = make_float4(0.f, 0.f, 0.f, 0.f);
            if (row < M) v = *(const float4*)(A1 + (size_t)row * 128 + kq * 4);
            uint32_t* p = &As[0][r][kq * 4];
            p[0] = f2tf32(v.x); p[1] = f2tf32(v.y);
            p[2] = f2tf32(v.z); p[3] = f2tf32(v.w);
        }
#pragma unroll
        for (int i = 0; i < NB4; i++) {
            int f = tid + i * 256;
            int kk = f / (BN / 4), cc = f % (BN / 4);
            float4 v = *(const float4*)(W1 + (size_t)kk * BN + cc * 4);
            uint32_t* p = &Bs[0][kk][cc * 4];
            p[0] = f2tf32(v.x); p[1] = f2tf32(v.y);
            p[2] = f2tf32(v.z); p[3] = f2tf32(v.w);
        }
    }
    __syncthreads();

    // ---- main loop over 16 stages ----
#pragma unroll 1
    for (int s = 0; s < NS; s++) {
        const int buf = s & 1;

        // prefetch stage s+1 into registers
        if (s + 1 < NS) {
            const float* A = (s + 1 < 8) ? A1 : A2;
            const float* W = (s + 1 < 8) ? W1 : W2;
            const int k0 = ((s + 1) & 7) * KT;
#pragma unroll
            for (int i = 0; i < 2; i++) {
                int f = tid + i * 256;
                int r = f >> 2, kq = f & 3;
                int row = rowBase + r;
                ra[i] = make_float4(0.f, 0.f, 0.f, 0.f);
                if (row < M) ra[i] = *(const float4*)(A + (size_t)row * 128 + k0 + kq * 4);
            }
#pragma unroll
            for (int i = 0; i < NB4; i++) {
                int f = tid + i * 256;
                int kk = f / (BN / 4), cc = f % (BN / 4);
                rb[i] = *(const float4*)(W + (size_t)(k0 + kk) * BN + cc * 4);
            }
        }

        // compute: 2 k8-steps on buf
#pragma unroll
        for (int k8 = 0; k8 < 2; k8++) {
            const int kb = k8 * 8;
            uint32_t a[2][4];
#pragma unroll
            for (int mf = 0; mf < 2; mf++) {
                int r0 = warpM * 32 + mf * 16 + g;
                a[mf][0] = As[buf][r0][kb + t4];
                a[mf][1] = As[buf][r0 + 8][kb + t4];
                a[mf][2] = As[buf][r0][kb + t4 + 4];
                a[mf][3] = As[buf][r0 + 8][kb + t4 + 4];
            }
#pragma unroll
            for (int nf = 0; nf < NF; nf++) {
                int cb = warpN * (BN / 2) + nf * 8 + g;
                uint32_t b0 = Bs[buf][kb + t4][cb];
                uint32_t b1 = Bs[buf][kb + t4 + 4][cb];
#pragma unroll
                for (int mf = 0; mf < 2; mf++) {
                    mma_tf32(acc[mf][nf][0], acc[mf][nf][1],
                             acc[mf][nf][2], acc[mf][nf][3],
                             a[mf][0], a[mf][1], a[mf][2], a[mf][3], b0, b1);
                }
            }
        }

        // store prefetched regs into other buffer
        if (s + 1 < NS) {
            const int nbuf = buf ^ 1;
#pragma unroll
            for (int i = 0; i < 2; i++) {
                int f = tid + i * 256;
                int r = f >> 2, kq = f & 3;
                uint32_t* p = &As[nbuf][r][kq * 4];
                p[0] = f2tf32(ra[i].x); p[1] = f2tf32(ra[i].y);
                p[2] = f2tf32(ra[i].z); p[3] = f2tf32(ra[i].w);
            }
#pragma unroll
            for (int i = 0; i < NB4; i++) {
                int f = tid + i * 256;
                int kk = f / (BN / 4), cc = f % (BN / 4);
                uint32_t* p = &Bs[nbuf][kk][cc * 4];
                p[0] = f2tf32(rb[i].x); p[1] = f2tf32(rb[i].y);
                p[2] = f2tf32(rb[i].z); p[3] = f2tf32(rb[i].w);
            }
            __syncthreads();
        }
    }

    // ---- epilogue: bias (+relu), write float2 per frag-row ----
#pragma unroll
    for (int nf = 0; nf < NF; nf++) {
        int col = warpN * (BN / 2) + nf * 8 + t4 * 2;
        float2 bv = *(const float2*)(bias + col);
#pragma unroll
        for (int mf = 0; mf < 2; mf++) {
            int r0 = rowBase + warpM * 32 + mf * 16 + g;
            float2 v0 = make_float2(acc[mf][nf][0] + bv.x, acc[mf][nf][1] + bv.y);
            float2 v1 = make_float2(acc[mf][nf][2] + bv.x, acc[mf][nf][3] + bv.y);
            if (RELU) {
                v0.x = fmaxf(v0.x, 0.f); v0.y = fmaxf(v0.y, 0.f);
                v1.x = fmaxf(v1.x, 0.f); v1.y = fmaxf(v1.y, 0.f);
            }
            if (r0 < M)     *(float2*)(out + (size_t)r0 * BN + col)       = v0;
            if (r0 + 8 < M) *(float2*)(out + (size_t)(r0 + 8) * BN + col) = v1;
        }
    }
}

// ---------------------------------------------------------------------------
// launch
// ---------------------------------------------------------------------------
extern "C" void kernel_launch(void* const* d_in, const int* in_sizes, int n_in,
                              void* d_out, int out_size) {
    const float* x   = (const float*)d_in[0];
    const int*   src = (const int*)d_in[1];
    const int*   dst = (const int*)d_in[2];
    const float* Ws0 = (const float*)d_in[3];
    const float* Wn0 = (const float*)d_in[4];
    const float* b0  = (const float*)d_in[5];
    const float* Ws1 = (const float*)d_in[6];
    const float* Wn1 = (const float*)d_in[7];
    const float* b1  = (const float*)d_in[8];
    const float* Ws2 = (const float*)d_in[9];
    const float* Wn2 = (const float*)d_in[10];
    const float* b2  = (const float*)d_in[11];
    float* out = (float*)d_out;

    const int M = in_sizes[0] / 128;   // 100000
    const int E = in_sizes[1];         // 1600000

    float *h1, *h2, *agg, *invdeg;
    int *degi, *rowstart, *cursor, *colsrc;
    cudaGetSymbolAddress((void**)&h1,  g_h1);
    cudaGetSymbolAddress((void**)&h2,  g_h2);
    cudaGetSymbolAddress((void**)&agg, g_agg);
    cudaGetSymbolAddress((void**)&invdeg, g_invdeg);
    cudaGetSymbolAddress((void**)&degi, g_degi);
    cudaGetSymbolAddress((void**)&rowstart, g_rowstart);
    cudaGetSymbolAddress((void**)&cursor, g_cursor);
    cudaGetSymbolAddress((void**)&colsrc, g_colsrc);

    const int gemmBlocks   = (M + 127) / 128;
    const int edgeBlocks   = (E + 255) / 256;
    const int gatherBlocks = (M * 32 + 255) / 256;   // warp per node

    // ---- CSR build (dst-sorted) ----
    cudaMemsetAsync(degi, 0, (size_t)M * sizeof(int));
    cudaMemsetAsync(cursor, 0, (size_t)M * sizeof(int));
    count_deg_kernel<<<edgeBlocks, 256>>>(dst, degi, E);
    scan_kernel<<<1, SCAN_THREADS>>>(degi, rowstart, invdeg, M);
    fill_kernel<<<edgeBlocks, 256>>>(src, dst, rowstart, cursor, colsrc, E);

    // ---- layer 0: h1 = relu(x@Ws0 + agg(x)@Wn0 + b0) ----
    gather_kernel<<<gatherBlocks, 256>>>(x, rowstart, colsrc, invdeg, agg, M);
    gemm_tc_kernel<128, true><<<gemmBlocks, 256>>>(x, agg, Ws0, Wn0, b0, h1, M);

    // ---- layer 1 ----
    gather_kernel<<<gatherBlocks, 256>>>(h1, rowstart, colsrc, invdeg, agg, M);
    gemm_tc_kernel<128, true><<<gemmBlocks, 256>>>(h1, agg, Ws1, Wn1, b1, h2, M);

    // ---- layer 2 (no relu, BN=64) ----
    gather_kernel<<<gatherBlocks, 256>>>(h2, rowstart, colsrc, invdeg, agg, M);
    gemm_tc_kernel<64, false><<<gemmBlocks, 256>>>(h2, agg, Ws2, Wn2, b2, out, M);
}